// round 1
// baseline (speedup 1.0000x reference)
#include <cuda_runtime.h>
#include <math.h>

#define Nn   100000
#define Ee   1600000
#define INC  256
#define Hh   64
#define OUTC 40
#define NH   (Nn * Hh)   // 6,400,000

// Scratch (static device globals; no allocations allowed)
__device__ float g_dinv[Nn];
__device__ float g_hb[3][NH];          // 0: h0, 1/2: ping-pong propagation buffers
__device__ float g_seq[(size_t)Nn * 4 * Hh];  // [N, 4, 64] token sequence

// ---------------- degree / norm ----------------
__global__ void k_deg_init() {
    int i = blockIdx.x * blockDim.x + threadIdx.x;
    if (i < Nn) g_dinv[i] = 1.0f;           // self-loop contributes 1
}
__global__ void k_deg_acc(const int* __restrict__ dst) {
    int e = blockIdx.x * blockDim.x + threadIdx.x;
    if (e < Ee) atomicAdd(&g_dinv[dst[e]], 1.0f);
}
__global__ void k_deg_fin() {
    int i = blockIdx.x * blockDim.x + threadIdx.x;
    if (i < Nn) g_dinv[i] = rsqrtf(g_dinv[i]);   // deg >= 1 always (self-loop)
}

// ---------------- h0 = relu(x @ W_in^T + b_in); also writes seq slot 0 ----------------
__global__ void k_in_linear(const float* __restrict__ x, const float* __restrict__ W,
                            const float* __restrict__ b) {
    extern __shared__ float sm[];
    float* Wt = sm;            // [256][64], Wt[k*64+j] = W[j*256+k]
    float* bb = Wt + 16384;    // 64
    float* xb = bb + 64;       // 8 warps * 256
    int tid = threadIdx.x;
    for (int i = tid; i < 16384; i += 256) {
        int k = i >> 6, j = i & 63;
        Wt[i] = W[j * INC + k];
    }
    if (tid < 64) bb[tid] = b[tid];
    __syncthreads();
    int warp = tid >> 5, l = tid & 31;
    float* xw = xb + warp * 256;
    for (int row = blockIdx.x * 8 + warp; row < Nn; row += gridDim.x * 8) {
        const float4* xg = (const float4*)(x + (size_t)row * INC);
        ((float4*)xw)[l]      = xg[l];
        ((float4*)xw)[l + 32] = xg[l + 32];
        __syncwarp();
        float a0 = bb[l], a1 = bb[l + 32];
        #pragma unroll 8
        for (int k = 0; k < 256; k++) {
            float xk = xw[k];
            a0 = fmaf(xk, Wt[k * 64 + l],      a0);
            a1 = fmaf(xk, Wt[k * 64 + l + 32], a1);
        }
        a0 = fmaxf(a0, 0.f); a1 = fmaxf(a1, 0.f);
        g_hb[0][(size_t)row * 64 + l]      = a0;
        g_hb[0][(size_t)row * 64 + l + 32] = a1;
        g_seq[(size_t)row * 256 + l]       = a0;
        g_seq[(size_t)row * 256 + l + 32]  = a1;
        __syncwarp();
    }
}

// ---------------- propagation: out = dinv^2 * in (self loop) then scatter edges ----------------
__global__ void k_prop_init(int inb, int outb) {
    int idx = blockIdx.x * blockDim.x + threadIdx.x;     // over NH/4 float4s
    if (idx < NH / 4) {
        float d = g_dinv[idx >> 4];
        float w = d * d;
        float4 v = ((const float4*)g_hb[inb])[idx];
        v.x *= w; v.y *= w; v.z *= w; v.w *= w;
        ((float4*)g_hb[outb])[idx] = v;
    }
}

__global__ void k_prop_edges(const int* __restrict__ src, const int* __restrict__ dst,
                             int inb, int outb) {
    long tid = (long)blockIdx.x * blockDim.x + threadIdx.x;
    int e = (int)(tid >> 4);
    if (e >= Ee) return;
    int q = (int)tid & 15;
    int s = __ldg(src + e), d = __ldg(dst + e);
    float w = g_dinv[s] * g_dinv[d];
    float4 v = ((const float4*)(g_hb[inb] + (size_t)s * 64))[q];
    float* p = g_hb[outb] + (size_t)d * 64 + q * 4;
    asm volatile("red.global.add.v4.f32 [%0], {%1,%2,%3,%4};"
                 :: "l"(p), "f"(v.x * w), "f"(v.y * w), "f"(v.z * w), "f"(v.w * w)
                 : "memory");
}

// ---------------- token = relu(p @ sg_W[k]^T + sg_b[k]) into seq slot ----------------
__global__ void k_tok(int inb, const float* __restrict__ W, const float* __restrict__ b, int slot) {
    __shared__ float Wt[4096];     // [64][64] transposed
    __shared__ float bb[64];
    __shared__ float xb[8 * 64];
    int tid = threadIdx.x;
    for (int i = tid; i < 4096; i += 256) {
        int k = i >> 6, j = i & 63;
        Wt[i] = W[j * 64 + k];
    }
    if (tid < 64) bb[tid] = b[tid];
    __syncthreads();
    int warp = tid >> 5, l = tid & 31;
    float* xw = xb + warp * 64;
    const float* pin = g_hb[inb];
    for (int row = blockIdx.x * 8 + warp; row < Nn; row += gridDim.x * 8) {
        xw[l]      = pin[(size_t)row * 64 + l];
        xw[l + 32] = pin[(size_t)row * 64 + l + 32];
        __syncwarp();
        float a0 = bb[l], a1 = bb[l + 32];
        #pragma unroll 8
        for (int k = 0; k < 64; k++) {
            float xk = xw[k];
            a0 = fmaf(xk, Wt[k * 64 + l],      a0);
            a1 = fmaf(xk, Wt[k * 64 + l + 32], a1);
        }
        float* op = g_seq + (size_t)row * 256 + slot * 64;
        op[l]      = fmaxf(a0, 0.f);
        op[l + 32] = fmaxf(a1, 0.f);
        __syncwarp();
    }
}

// ---------------- fused transformer layer + mean + classifier ----------------
// One warp per node. Lane layout: t = l>>3 (token 0..3), g = l&7 (8 lanes per token).
__global__ void __launch_bounds__(256, 1) k_former(
    const float* __restrict__ Wqkv_g, const float* __restrict__ bqkv_g,
    const float* __restrict__ Wout_g, const float* __restrict__ bout_g,
    const float* __restrict__ W1_g,   const float* __restrict__ b1_g,
    const float* __restrict__ W2_g,   const float* __restrict__ b2_g,
    const float* __restrict__ ln1w_g, const float* __restrict__ ln1b_g,
    const float* __restrict__ ln2w_g, const float* __restrict__ ln2b_g,
    const float* __restrict__ Wcls_g, const float* __restrict__ bcls_g,
    float* __restrict__ out)
{
    extern __shared__ float sm[];
    float* Wqkv = sm;             // 64*192, Wqkv[k*192+j] = Wqkv_g[j*64+k]
    float* Wout = Wqkv + 12288;   // 64*64
    float* W1   = Wout + 4096;    // 64*128
    float* W2   = W1 + 8192;      // 128*64
    float* Wcls = W2 + 8192;      // 64*40
    float* bqkv = Wcls + 2560;    // 192
    float* bout = bqkv + 192;     // 64
    float* b1   = bout + 64;      // 128
    float* b2   = b1 + 128;       // 64
    float* bcls = b2 + 64;        // 40
    float* ln1w = bcls + 40;      // 64
    float* ln1b = ln1w + 64;
    float* ln2w = ln1b + 64;
    float* ln2b = ln2w + 64;
    float* wbuf = ln2b + 64;      // per-warp scratch: 8 * 1616

    int tid = threadIdx.x;
    for (int i = tid; i < 12288; i += 256) { int k = i / 192, j = i % 192; Wqkv[i] = Wqkv_g[j * 64 + k]; }
    for (int i = tid; i < 4096;  i += 256) { int k = i >> 6,  j = i & 63;  Wout[i] = Wout_g[j * 64 + k]; }
    for (int i = tid; i < 8192;  i += 256) { int k = i >> 7,  j = i & 127; W1[i]   = W1_g[j * 64 + k]; }
    for (int i = tid; i < 8192;  i += 256) { int k = i >> 6,  j = i & 63;  W2[i]   = W2_g[j * 128 + k]; }
    for (int i = tid; i < 2560;  i += 256) { int k = i / 40,  j = i % 40;  Wcls[i] = Wcls_g[j * 64 + k]; }
    if (tid < 192) bqkv[tid] = bqkv_g[tid];
    if (tid < 128) b1[tid]   = b1_g[tid];
    if (tid < 64) {
        bout[tid] = bout_g[tid]; b2[tid] = b2_g[tid];
        ln1w[tid] = ln1w_g[tid]; ln1b[tid] = ln1b_g[tid];
        ln2w[tid] = ln2w_g[tid]; ln2b[tid] = ln2b_g[tid];
    }
    if (tid < 40) bcls[tid] = bcls_g[tid];
    __syncthreads();

    int warp = tid >> 5, l = tid & 31;
    float* s   = wbuf + warp * 1616;   // 256: seq tile / x1 / x2 residual chain
    float* q3  = s + 256;              // 768: qkv
    float* b2f = q3 + 768;             // 512: attn-out then gelu activations
    float* sc  = b2f + 512;            // 16: scores
    float* hb  = sc + 16;              // 64: pooled features
    const int t = l >> 3, g = l & 7;
    const float* srow = s + t * 64;
    float* srw = s + t * 64;

    for (int n = blockIdx.x * 8 + warp; n < Nn; n += gridDim.x * 8) {
        const float4* sp = (const float4*)(g_seq + (size_t)n * 256);
        ((float4*)s)[l]      = sp[l];
        ((float4*)s)[l + 32] = sp[l + 32];
        __syncwarp();

        // ---- QKV: lane computes 24 outputs j = g + 8i for its token ----
        float acc[24];
        #pragma unroll
        for (int i = 0; i < 24; i++) acc[i] = bqkv[g + 8 * i];
        for (int k = 0; k < 64; k++) {
            float sk = srow[k];
            const float* wr = Wqkv + k * 192 + g;
            #pragma unroll
            for (int i = 0; i < 24; i++) acc[i] = fmaf(sk, wr[8 * i], acc[i]);
        }
        #pragma unroll
        for (int i = 0; i < 24; i++) q3[t * 192 + g + 8 * i] = acc[i];
        __syncwarp();

        // ---- scores (4x4) + softmax ----
        if (l < 16) {
            const float* qp = q3 + (l >> 2) * 192;
            const float* kp = q3 + (l & 3) * 192 + 64;
            float d = 0.f;
            #pragma unroll
            for (int k = 0; k < 64; k++) d = fmaf(qp[k], kp[k], d);
            sc[l] = d * 0.125f;
        }
        __syncwarp();
        if (l < 4) {
            float s0 = sc[l*4], s1 = sc[l*4+1], s2 = sc[l*4+2], s3 = sc[l*4+3];
            float m = fmaxf(fmaxf(s0, s1), fmaxf(s2, s3));
            float e0 = __expf(s0 - m), e1 = __expf(s1 - m), e2 = __expf(s2 - m), e3 = __expf(s3 - m);
            float inv = 1.f / (e0 + e1 + e2 + e3);
            sc[l*4] = e0*inv; sc[l*4+1] = e1*inv; sc[l*4+2] = e2*inv; sc[l*4+3] = e3*inv;
        }
        __syncwarp();

        // ---- attn @ V ----
        {
            float w0 = sc[t*4+0], w1 = sc[t*4+1], w2 = sc[t*4+2], w3 = sc[t*4+3];
            #pragma unroll
            for (int i = 0; i < 8; i++) {
                int h = g + 8 * i;
                float v = w0 * q3[128 + h] + w1 * q3[320 + h] + w2 * q3[512 + h] + w3 * q3[704 + h];
                b2f[t * 64 + h] = v;
            }
        }
        __syncwarp();

        // ---- out proj + residual + LN1 (overwrite s with x1) ----
        {
            float r[8];
            #pragma unroll
            for (int i = 0; i < 8; i++) r[i] = bout[g + 8 * i];
            const float* arow = b2f + t * 64;
            for (int k = 0; k < 64; k++) {
                float ak = arow[k];
                const float* wr = Wout + k * 64 + g;
                #pragma unroll
                for (int i = 0; i < 8; i++) r[i] = fmaf(ak, wr[8 * i], r[i]);
            }
            float sum = 0.f;
            #pragma unroll
            for (int i = 0; i < 8; i++) { r[i] += srow[g + 8 * i]; sum += r[i]; }
            sum += __shfl_xor_sync(0xffffffffu, sum, 1);
            sum += __shfl_xor_sync(0xffffffffu, sum, 2);
            sum += __shfl_xor_sync(0xffffffffu, sum, 4);
            float mean = sum * 0.015625f;
            float sq = 0.f;
            #pragma unroll
            for (int i = 0; i < 8; i++) { float dd = r[i] - mean; sq = fmaf(dd, dd, sq); }
            sq += __shfl_xor_sync(0xffffffffu, sq, 1);
            sq += __shfl_xor_sync(0xffffffffu, sq, 2);
            sq += __shfl_xor_sync(0xffffffffu, sq, 4);
            float inv = rsqrtf(sq * 0.015625f + 1e-5f);
            #pragma unroll
            for (int i = 0; i < 8; i++) {
                int j = g + 8 * i;
                srw[j] = (r[i] - mean) * inv * ln1w[j] + ln1b[j];
            }
        }
        __syncwarp();

        // ---- FF1 + exact gelu ----
        {
            float ga[16];
            #pragma unroll
            for (int i = 0; i < 16; i++) ga[i] = b1[g + 8 * i];
            for (int k = 0; k < 64; k++) {
                float xk = srow[k];
                const float* wr = W1 + k * 128 + g;
                #pragma unroll
                for (int i = 0; i < 16; i++) ga[i] = fmaf(xk, wr[8 * i], ga[i]);
            }
            #pragma unroll
            for (int i = 0; i < 16; i++) {
                float xg = ga[i];
                b2f[t * 128 + g + 8 * i] = 0.5f * xg * (1.0f + erff(xg * 0.70710678118f));
            }
        }
        __syncwarp();

        // ---- FF2 + residual + LN2 + token mean ----
        {
            float f[8];
            #pragma unroll
            for (int i = 0; i < 8; i++) f[i] = b2[g + 8 * i];
            const float* grow = b2f + t * 128;
            for (int k = 0; k < 128; k++) {
                float gk = grow[k];
                const float* wr = W2 + k * 64 + g;
                #pragma unroll
                for (int i = 0; i < 8; i++) f[i] = fmaf(gk, wr[8 * i], f[i]);
            }
            float sum = 0.f;
            #pragma unroll
            for (int i = 0; i < 8; i++) { f[i] += srow[g + 8 * i]; sum += f[i]; }
            sum += __shfl_xor_sync(0xffffffffu, sum, 1);
            sum += __shfl_xor_sync(0xffffffffu, sum, 2);
            sum += __shfl_xor_sync(0xffffffffu, sum, 4);
            float mean = sum * 0.015625f;
            float sq = 0.f;
            #pragma unroll
            for (int i = 0; i < 8; i++) { float dd = f[i] - mean; sq = fmaf(dd, dd, sq); }
            sq += __shfl_xor_sync(0xffffffffu, sq, 1);
            sq += __shfl_xor_sync(0xffffffffu, sq, 2);
            sq += __shfl_xor_sync(0xffffffffu, sq, 4);
            float inv = rsqrtf(sq * 0.015625f + 1e-5f);
            #pragma unroll
            for (int i = 0; i < 8; i++) {
                int j = g + 8 * i;
                float x2 = (f[i] - mean) * inv * ln2w[j] + ln2b[j];
                x2 += __shfl_xor_sync(0xffffffffu, x2, 8);
                x2 += __shfl_xor_sync(0xffffffffu, x2, 16);
                if (t == 0) hb[j] = x2 * 0.25f;
            }
        }
        __syncwarp();

        // ---- classifier: 40 outputs ----
        {
            float o0 = bcls[l];
            float o1 = (l < 8) ? bcls[32 + l] : 0.f;
            for (int k = 0; k < 64; k++) {
                float hk = hb[k];
                o0 = fmaf(hk, Wcls[k * 40 + l], o0);
                o1 = fmaf(hk, Wcls[k * 40 + 32 + (l & 7)], o1);
            }
            out[(size_t)n * 40 + l] = o0;
            if (l < 8) out[(size_t)n * 40 + 32 + l] = o1;
        }
        __syncwarp();
    }
}

extern "C" void kernel_launch(void* const* d_in, const int* in_sizes, int n_in,
                              void* d_out, int out_size) {
    const float* x     = (const float*)d_in[0];
    const int*   ei    = (const int*)d_in[1];
    const float* W_in  = (const float*)d_in[2];
    const float* b_in  = (const float*)d_in[3];
    const float* sg_W  = (const float*)d_in[4];
    const float* sg_b  = (const float*)d_in[5];
    const float* Wqkv  = (const float*)d_in[6];
    const float* bqkv  = (const float*)d_in[7];
    const float* Wout  = (const float*)d_in[8];
    const float* bout  = (const float*)d_in[9];
    const float* W1    = (const float*)d_in[10];
    const float* b1    = (const float*)d_in[11];
    const float* W2    = (const float*)d_in[12];
    const float* b2    = (const float*)d_in[13];
    const float* ln1w  = (const float*)d_in[14];
    const float* ln1b  = (const float*)d_in[15];
    const float* ln2w  = (const float*)d_in[16];
    const float* ln2b  = (const float*)d_in[17];
    const float* Wcls  = (const float*)d_in[18];
    const float* bcls  = (const float*)d_in[19];
    float* out = (float*)d_out;

    cudaFuncSetAttribute(k_in_linear, cudaFuncAttributeMaxDynamicSharedMemorySize, 73984);
    cudaFuncSetAttribute(k_former,    cudaFuncAttributeMaxDynamicSharedMemorySize, 196000);

    // degree / dinv
    k_deg_init<<<(Nn + 255) / 256, 256>>>();
    k_deg_acc<<<(Ee + 255) / 256, 256>>>(ei + Ee);
    k_deg_fin<<<(Nn + 255) / 256, 256>>>();

    // h0 + seq slot 0
    k_in_linear<<<444, 256, 73984>>>(x, W_in, b_in);

    // 3 hops: buffers 0 -> 1 -> 2 -> 1
    const int inb[3]  = {0, 1, 2};
    const int outb[3] = {1, 2, 1};
    for (int hop = 0; hop < 3; hop++) {
        k_prop_init<<<(NH / 4 + 255) / 256, 256>>>(inb[hop], outb[hop]);
        k_prop_edges<<<(Ee * 16) / 256, 256>>>(ei, ei + Ee, inb[hop], outb[hop]);
        k_tok<<<1024, 256>>>(outb[hop], sg_W + hop * 4096, sg_b + hop * 64, hop + 1);
    }

    // fused transformer + pooling + classifier
    k_former<<<152, 256, 196000>>>(Wqkv, bqkv, Wout, bout, W1, b1, W2, b2,
                                   ln1w, ln1b, ln2w, ln2b, Wcls, bcls, out);
}